// round 14
// baseline (speedup 1.0000x reference)
#include <cuda_runtime.h>
#include <math.h>

#define NMOL   32
#define NATOM  128
#define DEG    32
#define NTOT   4096
#define NPAIR  131072
#define NSENS  20
#define NF1    20
#define TM     32          // atoms owned per k_step block
#define EPS2   34          // envP row stride in u64 units
#define SROW   648         // padded sense row (floats) = 162 float4

typedef unsigned long long u64t;

// ---------------- scratch (device globals; no allocation) ----------------
__device__ float  g_sense[NPAIR * NSENS];    // [pair][s]
__device__ float  g_indf [NTOT * 5];         // [atom][5]
__device__ float  g_ct   [NTOT * NF1];       // in-place (owner block only)
__device__ float  g_h    [2 * NTOT * NF1];   // parity double buffer
__device__ float  g_x0   [2 * NTOT];         // parity double buffer
__device__ float  g_xt   [NTOT * NF1];       // x_t written by k_xt, read by k_step
__device__ float2 g_wpair [400 * 80];        // Wint paired over (s_even, s_odd)
__device__ float2 g_wspair[20 * 80];         // Wself paired over (f_even, f_odd)

__device__ __forceinline__ float softplusf(float x) {
    return fmaxf(x, 0.f) + log1pf(expf(-fabsf(x)));
}
__device__ __forceinline__ float sigmoidf(float x) {
    return 1.f / (1.f + expf(-x));
}
__device__ __forceinline__ u64t packdup(float x) {
    u64t r; asm("mov.b64 %0, {%1, %1};" : "=l"(r) : "f"(x)); return r;
}
__device__ __forceinline__ void ffma2(u64t& d, u64t a, u64t b) {
    asm("fma.rn.f32x2 %0, %1, %2, %0;" : "+l"(d) : "l"(a), "l"(b));
}
__device__ __forceinline__ void fadd2(u64t& d, u64t a) {
    asm("add.rn.f32x2 %0, %0, %1;" : "+l"(d) : "l"(a));
}
__device__ __forceinline__ void unpack2(u64t v, float& lo, float& hi) {
    asm("mov.b64 {%0, %1}, %2;" : "=f"(lo), "=f"(hi) : "l"(v));
}

// ---------------- one-time prep: sense (smem-staged stores) + indf + weight pairing ----
__global__ void k_prep(const int* __restrict__ species, const float* __restrict__ x_h,
                       const float* __restrict__ coord, const int* __restrict__ ps,
                       const float* __restrict__ Wint, const float* __restrict__ Wself) {
    __shared__ float sbuf[256 * 20];
    int t = threadIdx.x;
    int p = blockIdx.x * 256 + t;   // [0, NPAIR)

    {
        int a = p >> 5;
        int b = ps[p];
        float dx = coord[a * 3 + 0] - coord[b * 3 + 0];
        float dy = coord[a * 3 + 1] - coord[b * 3 + 1];
        float dz = coord[a * 3 + 2] - coord[b * 3 + 2];
        float d = sqrtf(dx * dx + dy * dy + dz * dz + 1e-12f);
        float cut = 0.f;
        if (d < 7.5f) { float c = cospif(d * (1.f / 15.f)); cut = c * c; }
        const float m0 = 0.2f;
        const float m1 = 1.f / 0.7f;
        const float invsig = 20.f / (m1 - m0);
        const float delta = 20.f / 19.f;
        float z0 = (1.f / d - m0) * invsig;

        float ss = floorf(z0 / delta + 0.5f);
        ss = fminf(fmaxf(ss, 0.f), 19.f);
        int sstar = (int)ss;
        float zs = z0 - ss * delta;

        float Cd = expf(-delta * delta);
        float E  = cut * expf(-0.5f * zs * zs);
        float* o = sbuf + t * 20;
        o[sstar] = E;
        float Eu = E;
        float uu = expf(delta * zs - 0.5f * delta * delta);
        for (int s = sstar + 1; s < 20; s++) { Eu *= uu; uu *= Cd; o[s] = Eu; }
        float Ed = E;
        float dd = expf(-delta * zs - 0.5f * delta * delta);
        for (int s = sstar - 1; s >= 0; s--) { Ed *= dd; dd *= Cd; o[s] = Ed; }
    }
    __syncthreads();
    {
        float4* dst = (float4*)(g_sense + (size_t)blockIdx.x * 5120);
        const float4* src = (const float4*)sbuf;
        for (int i = t; i < 1280; i += 256) dst[i] = src[i];
    }

    if (p < NTOT) {
        int sp = species[p];
        g_indf[p * 5 + 0] = (sp == 1) ? 1.f : 0.f;
        g_indf[p * 5 + 1] = (sp == 8) ? 1.f : 0.f;
        g_indf[p * 5 + 2] = x_h[p * 3 + 0];
        g_indf[p * 5 + 3] = x_h[p * 3 + 1];
        g_indf[p * 5 + 4] = x_h[p * 3 + 2];
    }

    if (p < 32000) {
        int pr = p / 80, g = p % 80;
        int s2 = pr / 40, f = pr % 40;
        int lo = 2 * s2 * 40 + f;
        g_wpair[p] = make_float2(Wint[lo * 80 + g], Wint[(lo + 40) * 80 + g]);
    } else if (p < 32000 + 1600) {
        int i2 = p - 32000;
        int fp = i2 / 80, g = i2 % 80;
        g_wspair[i2] = make_float2(Wself[(2 * fp) * 80 + g], Wself[(2 * fp + 1) * 80 + g]);
    }
}

// ---------------- f0 hipnn (runs once, block-tiled): writes c_t, g_h[0] ----------------
#define SMEM_F0_FLOATS 37448
#define SMEM_F0_BYTES  (SMEM_F0_FLOATS * 4)

__global__ void __launch_bounds__(256, 1)
k_f0(const int* __restrict__ ps,
     const float* __restrict__ iw, const float* __restrict__ sw,
     const float* __restrict__ sb, const float* __restrict__ aw,
     const float* __restrict__ ab) {
    extern __shared__ float sm[];
    float* s_sense = sm;
    float* s_senv  = sm + 20736;
    float* s_indf  = sm + 24064;
    float* s_iw    = sm + 24704;
    float* s_sw    = sm + 28704;
    float* s_sb    = sm + 28904;
    float* s_aw    = sm + 28944;
    float* s_ab    = sm + 33744;
    float* s_sy    = sm + 33864;
    float* s_sy2   = sm + 35144;
    int*   s_nb    = (int*)(sm + 36424);

    int t  = threadIdx.x;
    int A0 = blockIdx.x * TM;
    int MB = (A0 / NATOM) * NATOM;
    int L0 = A0 - MB;

    for (int i = t; i < 1024; i += 256) s_nb[i] = ps[A0 * 32 + i] - MB;
    for (int i = t; i < 640;  i += 256) s_indf[i] = g_indf[MB * 5 + i];
    for (int i = t; i < 4000; i += 256) s_iw[i] = iw[i];
    for (int i = t; i < 4800; i += 256) s_aw[i] = aw[i];
    if (t < 200) s_sw[t] = sw[t];
    if (t >= 216 && t < 256) s_sb[t - 216] = sb[t - 216];
    for (int i = t; i < 120; i += 256) s_ab[i] = ab[i];
    {
        const float4* src = (const float4*)(g_sense + (size_t)A0 * 640);
        float4* dst = (float4*)s_sense;
        for (int q = 0; q < 20; q++) {
            int i = t + q * 256;
            int row = i / 160, col = i - row * 160;
            dst[row * 162 + col] = src[i];
        }
    }
    __syncthreads();

    {
        int aL = t >> 3;
        int r  = t & 7;
        u64t acc[10][5];
#pragma unroll
        for (int q = 0; q < 10; q++)
#pragma unroll
            for (int f = 0; f < 5; f++) acc[q][f] = 0ULL;
#pragma unroll
        for (int j = 0; j < 4; j++) {
            int k = r + j * 8;
            int nb = s_nb[aL * 32 + k];
            const float* xp = s_indf + nb * 5;
            u64t xd[5];
#pragma unroll
            for (int f = 0; f < 5; f++) xd[f] = packdup(xp[f]);
            const ulonglong2* spp = (const ulonglong2*)(s_sense + aL * SROW + k * 20);
#pragma unroll
            for (int q = 0; q < 5; q++) {
                ulonglong2 sv = spp[q];
#pragma unroll
                for (int f = 0; f < 5; f++) {
                    ffma2(acc[q * 2 + 0][f], sv.x, xd[f]);
                    ffma2(acc[q * 2 + 1][f], sv.y, xd[f]);
                }
            }
        }
#pragma unroll
        for (int d = 4; d >= 1; d >>= 1)
#pragma unroll
            for (int q = 0; q < 10; q++)
#pragma unroll
                for (int f = 0; f < 5; f++) {
                    u64t o = __shfl_down_sync(0xFFFFFFFFu, acc[q][f], d);
                    fadd2(acc[q][f], o);
                }
        if (r == 0) {
#pragma unroll
            for (int q = 0; q < 10; q++)
#pragma unroll
                for (int f = 0; f < 5; f++) {
                    float lo, hi;
                    unpack2(acc[q][f], lo, hi);
                    s_senv[aL * 104 + (2 * q)     * 5 + f] = lo;
                    s_senv[aL * 104 + (2 * q + 1) * 5 + f] = hi;
                }
        }
    }
    __syncthreads();

    {
        int a  = t >> 3;
        int j0 = (t & 7) * 5;
        float pre[5];
#pragma unroll
        for (int jj = 0; jj < 5; jj++) pre[jj] = s_sb[j0 + jj];
        const float* xo = s_indf + (L0 + a) * 5;
#pragma unroll
        for (int f = 0; f < 5; f++) {
            float xv = xo[f];
#pragma unroll
            for (int jj = 0; jj < 5; jj++) pre[jj] += xv * s_sw[f * 40 + j0 + jj];
        }
        for (int e = 0; e < 100; e++) {
            float ev = s_senv[a * 104 + e];
#pragma unroll
            for (int jj = 0; jj < 5; jj++) pre[jj] += ev * s_iw[e * 40 + j0 + jj];
        }
#pragma unroll
        for (int jj = 0; jj < 5; jj++) s_sy[a * 40 + j0 + jj] = softplusf(pre[jj]);
        __syncthreads();

        float* src = s_sy; float* dst = s_sy2;
        for (int l = 0; l < 3; l++) {
            float v[5];
#pragma unroll
            for (int jj = 0; jj < 5; jj++) v[jj] = s_ab[l * 40 + j0 + jj];
            for (int i = 0; i < 40; i++) {
                float yv = src[a * 40 + i];
#pragma unroll
                for (int jj = 0; jj < 5; jj++) v[jj] += yv * s_aw[l * 1600 + i * 40 + j0 + jj];
            }
            __syncthreads();
#pragma unroll
            for (int jj = 0; jj < 5; jj++) dst[a * 40 + j0 + jj] = softplusf(v[jj]);
            __syncthreads();
            float* tp = src; src = dst; dst = tp;
        }
        for (int idx = t; idx < 640; idx += 256) {
            int a2 = idx / 20, j = idx % 20;
            g_ct[(A0 + a2) * 20 + j] = src[a2 * 40 + j];
            g_h[(A0 + a2) * 20 + j]  = src[a2 * 40 + 20 + j];
        }
    }
}

// ---------------- per-step x_t kernel: own 32 atoms, computed once ----------------
__global__ void __launch_bounds__(256, 2)
k_xt(const int* __restrict__ ps, const float* __restrict__ x_raw, int mode,
     const float* __restrict__ h1_iw, const float* __restrict__ h1_sw,
     const float* __restrict__ h1_sb, const float* __restrict__ h1_aw,
     const float* __restrict__ h1_ab, int parity) {
    __shared__ float s_xin[128];
    __shared__ float s_iw[400], s_sw[20], s_sb[20], s_aw[1200], s_ab[60];
    __shared__ float s_env[640], s_y[640], s_y2[640];

    int t  = threadIdx.x;
    int A0 = blockIdx.x * TM;
    int MB = (A0 / NATOM) * NATOM;
    int L0 = A0 - MB;
    const float* x0_r = g_x0 + parity * NTOT;

    if (t < 128) {
        int n = MB + t;
        s_xin[t] = (mode < 2) ? x_raw[n * 2 + mode] : x0_r[n];
    }
    for (int i = t; i < 400;  i += 256) s_iw[i] = h1_iw[i];
    for (int i = t; i < 1200; i += 256) s_aw[i] = h1_aw[i];
    if (t >= 160 && t < 180) { s_sw[t - 160] = h1_sw[t - 160]; s_sb[t - 160] = h1_sb[t - 160]; }
    if (t >= 192 && t < 252) s_ab[t - 192] = h1_ab[t - 192];
    __syncthreads();

    {
        int i = t >> 3;
        int r = t & 7;
        int p0 = (A0 + i) * 32;
        u64t acc[10];
#pragma unroll
        for (int s = 0; s < 10; s++) acc[s] = 0ULL;
#pragma unroll
        for (int j = 0; j < 4; j++) {
            int k = r + j * 8;
            int p = p0 + k;
            int nb = ps[p] - MB;
            u64t xd = packdup(s_xin[nb]);
            const ulonglong2* sp = (const ulonglong2*)(g_sense + (size_t)p * 20);
#pragma unroll
            for (int q = 0; q < 5; q++) {
                ulonglong2 sv = sp[q];
                ffma2(acc[q * 2 + 0], sv.x, xd);
                ffma2(acc[q * 2 + 1], sv.y, xd);
            }
        }
#pragma unroll
        for (int d = 4; d >= 1; d >>= 1)
#pragma unroll
            for (int s = 0; s < 10; s++) {
                u64t o = __shfl_down_sync(0xFFFFFFFFu, acc[s], d, 8);
                fadd2(acc[s], o);
            }
        if (r == 0) {
#pragma unroll
            for (int s = 0; s < 10; s++) {
                float lo, hi;
                unpack2(acc[s], lo, hi);
                s_env[i * 20 + 2 * s]     = lo;
                s_env[i * 20 + 2 * s + 1] = hi;
            }
        }
    }
    __syncthreads();

    {
        int a  = t >> 2;
        int sh = (t & 3) * 5;
        bool act = (t < 128);
        if (act) {
            float xo = s_xin[L0 + a];
            float pre[5];
#pragma unroll
            for (int j = 0; j < 5; j++) pre[j] = s_sb[sh + j] + xo * s_sw[sh + j];
            for (int s2 = 0; s2 < 20; s2++) {
                float ev = s_env[a * 20 + s2];
#pragma unroll
                for (int j = 0; j < 5; j++) pre[j] += ev * s_iw[s2 * 20 + sh + j];
            }
#pragma unroll
            for (int j = 0; j < 5; j++) s_y[a * 20 + sh + j] = softplusf(pre[j]);
        }
        __syncthreads();

        float* src = s_y; float* dst = s_y2;
        for (int l = 0; l < 3; l++) {
            float v[5];
            if (act) {
#pragma unroll
                for (int j = 0; j < 5; j++) v[j] = s_ab[l * 20 + sh + j];
                for (int i2 = 0; i2 < 20; i2++) {
                    float yv = src[a * 20 + i2];
#pragma unroll
                    for (int j = 0; j < 5; j++) v[j] += yv * s_aw[(l * 20 + i2) * 20 + sh + j];
                }
            }
            __syncthreads();
            if (act) {
#pragma unroll
                for (int j = 0; j < 5; j++) dst[a * 20 + sh + j] = softplusf(v[j]);
            }
            __syncthreads();
            float* tp = src; src = dst; dst = tp;
        }
        if (act) {
#pragma unroll
            for (int j = 0; j < 5; j++) g_xt[(A0 + a) * 20 + sh + j] = src[a * 20 + sh + j];
        }
    }
}

// ---------------- fused per-step kernel: lane=atom broadcast-W GEMM ----------------
// SMEM (floats): s_xcat[0,5120) | s_envP[5120,32320) | s_work[32320,53056) | s_nb[53056,54080)
// s_work overlays: phase3 sense tile [0,20736);
//   GEMM: s_wc[0,10240) s_tmp[10240,12800) s_o[12800,13440) s_wsp[13440,16640)
#define SMEM_FLOATS (5120 + 27200 + 32 * SROW + 1024)
#define SMEM_BYTES  (SMEM_FLOATS * 4)

__global__ void __launch_bounds__(256, 1)
k_step(const int* __restrict__ ps,
       const float* __restrict__ Wb,
       const float* __restrict__ pw0, const float* __restrict__ pw1,
       const float* __restrict__ pb1,
       int outcol, float* __restrict__ out, int parity) {
    extern __shared__ float sm[];
    float* s_xcat = sm;                                    // 5120
    float* s_envPf = sm + 5120;                            // 27200
    u64t*  s_envP  = (u64t*)s_envPf;
    float* s_work = sm + 32320;                            // 20736
    int*   s_nb   = (int*)(sm + 53056);                    // 1024 ints

    float* s_wc  = s_work;          // GEMM W chunk (10240 floats)
    u64t*  s_wcu = (u64t*)s_wc;
    float* s_tmp = s_work + 10240;  // 2560
    float* s_o   = s_work + 12800;  // 640
    float* s_wsp = s_work + 13440;  // 3200 (staged g_wspair)
    u64t*  s_wspu = (u64t*)s_wsp;

    int t  = threadIdx.x;
    int A0 = blockIdx.x * TM;
    int MB = (A0 / NATOM) * NATOM;
    int L0 = A0 - MB;
    float* h_w = g_h + (parity ^ 1) * (NTOT * NF1);
    const float* h_r = g_h + parity * (NTOT * NF1);
    float* x0_w = g_x0 + (parity ^ 1) * NTOT;

    // ---- stage: xcat (x_t + h for whole molecule), nb, sense tile (own atoms) ----
    {
        const float4* xsrc = (const float4*)(g_xt + MB * NF1);
        const float4* hsrc = (const float4*)(h_r + MB * NF1);
        for (int i4 = t; i4 < 640; i4 += 256) {
            int a = i4 / 5, j = (i4 % 5) * 4;
            *(float4*)&s_xcat[a * 40 + j]      = xsrc[i4];
            *(float4*)&s_xcat[a * 40 + 20 + j] = hsrc[i4];
        }
    }
    for (int i = t; i < 1024; i += 256) s_nb[i] = ps[A0 * 32 + i] - MB;
    {
        const float4* src = (const float4*)(g_sense + (size_t)A0 * 640);
        float4* dst = (float4*)s_work;
        for (int q = 0; q < 20; q++) {
            int i = t + q * 256;
            int row = i / 160, col = i - row * 160;
            dst[row * 162 + col] = src[i];
        }
    }
    __syncthreads();

    // ---- phase 3: env (40 f) for my 32 atoms, packed s-pairs -> envP ----
    {
        int i  = t >> 3;
        int f0 = (t & 7) * 5;
        u64t acc[10][5];
#pragma unroll
        for (int sp = 0; sp < 10; sp++)
#pragma unroll
            for (int j = 0; j < 5; j++) acc[sp][j] = 0ULL;
        const float* sen = s_work + i * SROW;
        const int* nbp = s_nb + i * 32;
        for (int k = 0; k < 32; k++) {
            int nb = nbp[k];
            const float* xr = s_xcat + nb * 40 + f0;
            u64t xd[5];
#pragma unroll
            for (int j = 0; j < 5; j++) xd[j] = packdup(xr[j]);
            const ulonglong2* sk = (const ulonglong2*)(sen + k * 20);
#pragma unroll
            for (int q = 0; q < 5; q++) {
                ulonglong2 sv = sk[q];
#pragma unroll
                for (int j = 0; j < 5; j++) {
                    ffma2(acc[q * 2 + 0][j], sv.x, xd[j]);
                    ffma2(acc[q * 2 + 1][j], sv.y, xd[j]);
                }
            }
        }
#pragma unroll
        for (int sp = 0; sp < 10; sp++)
#pragma unroll
            for (int j = 0; j < 5; j++)
                s_envP[(sp * 40 + f0 + j) * EPS2 + i] = acc[sp][j];
    }
    __syncthreads();   // sense reads done + envP visible; s_work free

    // ---- phase 4: GEMM, lane=atom, warp owns 10 output cols (broadcast W) ----
    int wid  = t >> 5;        // 0..7
    int lane = t & 31;        // atom
    int gb   = wid * 10;      // first output col (u64 index into W rows)
    u64t acc[10];
#pragma unroll
    for (int j = 0; j < 10; j++) acc[j] = 0ULL;
    const float4* W4 = (const float4*)g_wpair;

    {   // stage chunk 0 + wspair
        for (int i = t; i < 2560; i += 256) ((float4*)s_wc)[i] = W4[i];
        const float4* wssrc = (const float4*)g_wspair;
        for (int i = t; i < 800; i += 256) ((float4*)s_wsp)[i] = wssrc[i];
    }
    __syncthreads();

    for (int c = 0; c < 7; c++) {
        int p0 = c * 64;
        int plen = (c < 6) ? 64 : 16;
        float4 pf[10];
        int nb4 = 0, pbase = 0;
        if (c < 6) {
            nb4 = ((c + 1 < 6) ? 64 : 16) * 40;
            pbase = (p0 + 64) * 40;
#pragma unroll
            for (int q = 0; q < 10; q++) {
                int i = t + q * 256;
                if (i < nb4) pf[q] = W4[pbase + i];
            }
        }
#pragma unroll 2
        for (int pp = 0; pp < plen; pp++) {
            u64t ev = s_envP[(p0 + pp) * EPS2 + lane];
            const ulonglong2* wr = (const ulonglong2*)&s_wcu[pp * 80 + gb];
#pragma unroll
            for (int q = 0; q < 5; q++) {
                ulonglong2 wv = wr[q];
                ffma2(acc[2 * q + 0], ev, wv.x);
                ffma2(acc[2 * q + 1], ev, wv.y);
            }
        }
        __syncthreads();
        if (c < 6) {
#pragma unroll
            for (int q = 0; q < 10; q++) {
                int i = t + q * 256;
                if (i < nb4) ((float4*)s_wc)[i] = pf[q];
            }
            __syncthreads();
        }
    }

    // self term: atom = lane, f-pairs from xcat x staged wspair (broadcast)
    {
        const u64t* xcp = (const u64t*)(s_xcat + (L0 + lane) * 40);
#pragma unroll 4
        for (int fp = 0; fp < 20; fp++) {
            u64t xp = xcp[fp];
            const ulonglong2* wr = (const ulonglong2*)&s_wspu[fp * 80 + gb];
#pragma unroll
            for (int q = 0; q < 5; q++) {
                ulonglong2 wv = wr[q];
                ffma2(acc[2 * q + 0], xp, wv.x);
                ffma2(acc[2 * q + 1], xp, wv.y);
            }
        }
    }

    // unpack + bias -> s_tmp
    {
        float* d = &s_tmp[lane * 80 + gb];
#pragma unroll
        for (int q = 0; q < 10; q++) {
            float lo, hi;
            unpack2(acc[q], lo, hi);
            d[q] = lo + hi + Wb[gb + q];
        }
    }
    __syncthreads();

    // ---- gates ----
    for (int idx = t; idx < TM * 20; idx += 256) {
        int i = idx / 20, j = idx % 20;
        int a = A0 + i;
        float t0v = s_tmp[i * 80 + j * 4 + 0];
        float t1v = s_tmp[i * 80 + j * 4 + 1];
        float t2v = s_tmp[i * 80 + j * 4 + 2];
        float t3v = s_tmp[i * 80 + j * 4 + 3];
        float o  = sigmoidf(t3v);
        float cn = sigmoidf(t1v) * g_ct[a * 20 + j] + sigmoidf(t0v) * tanhf(t2v);
        g_ct[a * 20 + j] = cn;
        h_w[a * 20 + j]  = o * tanhf(cn);
        s_o[i * 20 + j] = o;
    }
    __syncthreads();

    // ---- x0 epilogue ----
    if (t < TM) {
        int a = A0 + t;
        float x0v = pb1[0];
#pragma unroll
        for (int f = 0; f < 5; f++)  x0v += g_indf[a * 5 + f] * pw0[f];
#pragma unroll
        for (int j = 0; j < 20; j++) x0v += s_o[t * 20 + j] * pw1[j];
        x0_w[a] = x0v;
        if (outcol >= 0) out[a * 3 + outcol] = x0v;
    }
}

// ---------------- host ----------------
extern "C" void kernel_launch(void* const* d_in, const int* in_sizes, int n_in,
                              void* d_out, int out_size) {
    const int*   species = (const int*)d_in[0];
    const float* coords  = (const float*)d_in[1];
    const float* x_h     = (const float*)d_in[2];
    const float* x_raw   = (const float*)d_in[3];
    const int*   ps      = (const int*)d_in[5];
    const float* h0_iw   = (const float*)d_in[6];
    const float* h0_sw   = (const float*)d_in[7];
    const float* h0_sb   = (const float*)d_in[8];
    const float* h0_aw   = (const float*)d_in[9];
    const float* h0_ab   = (const float*)d_in[10];
    const float* h1_iw   = (const float*)d_in[11];
    const float* h1_sw   = (const float*)d_in[12];
    const float* h1_sb   = (const float*)d_in[13];
    const float* h1_aw   = (const float*)d_in[14];
    const float* h1_ab   = (const float*)d_in[15];
    const float* W_iw    = (const float*)d_in[16];
    const float* W_sw    = (const float*)d_in[17];
    const float* W_sb    = (const float*)d_in[18];
    const float* pw0     = (const float*)d_in[19];
    const float* pw1     = (const float*)d_in[20];
    const float* pb1     = (const float*)d_in[21];
    float* out = (float*)d_out;

    cudaFuncSetAttribute(k_step, cudaFuncAttributeMaxDynamicSharedMemorySize, SMEM_BYTES);
    cudaFuncSetAttribute(k_f0,   cudaFuncAttributeMaxDynamicSharedMemorySize, SMEM_F0_BYTES);

    k_prep<<<NPAIR / 256, 256>>>(species, x_h, coords, ps, W_iw, W_sw);
    k_f0<<<NTOT / TM, 256, SMEM_F0_BYTES>>>(ps, h0_iw, h0_sw, h0_sb, h0_aw, h0_ab);

    for (int s = 0; s < 5; s++) {
        int mode = (s < 2) ? s : 2;
        int outcol = (s >= 2) ? (s - 2) : -1;
        k_xt<<<NTOT / TM, 256>>>(ps, x_raw, mode,
                                 h1_iw, h1_sw, h1_sb, h1_aw, h1_ab, s & 1);
        k_step<<<NTOT / TM, 256, SMEM_BYTES>>>(ps, W_sb, pw0, pw1, pb1,
                                               outcol, out, s & 1);
    }
}